// round 1
// baseline (speedup 1.0000x reference)
#include <cuda_runtime.h>
#include <math.h>

// Problem constants (from reference): D_MODEL=300, L=512, B=512, OUT=4.
// Key insight: jnp.diagonal(fmap, axis1=0, axis2=1) keeps only
//   diag[e, i] = fmap[i, i, e] = sum_l e2[i,l,i] * e1[i,l,e]   for i in [0,300)
// so the 512x300x300 batched GEMM collapses to 300 weighted row-sums.

#define D   300
#define LSEQ 512
#define OUTC 4

// Scratch (no cudaMalloc allowed)
__device__ float g_pe[LSEQ * D];     // sinusoidal positional encoding [L, D]
__device__ float g_diag[D * D];      // diag matrix, layout [e][i]

// ---------------------------------------------------------------------------
// Kernel 0: positional encoding. 153600 elems, double-precision args for
// accurate sin/cos at large arguments (up to 511 rad).
// ---------------------------------------------------------------------------
__global__ void pe_kernel() {
    int idx = blockIdx.x * blockDim.x + threadIdx.x;
    if (idx >= LSEQ * D) return;
    int l = idx / D;
    int d = idx % D;
    int k = d >> 1;
    // div = exp(2k * (-ln(10000)/300))
    const double coef = -9.210340371976184 / (double)D;  // -ln(10000)/D
    double divv = exp((double)(2 * k) * coef);
    double ang  = (double)l * divv;
    g_pe[idx] = (d & 1) ? (float)cos(ang) : (float)sin(ang);
}

// ---------------------------------------------------------------------------
// Kernel 1: diag[e][i] for one i per block.
//   s[l]      = emb2[x2[i,l]][i]*scale + pe[l][i]
//   diag[e,i] = sum_l s[l] * (emb1[x1[i,l]][e]*scale + pe[l][e])
// 320 threads: phase A fills s[] / row offsets; phase B threads 0..299 each
// own one e (coalesced emb1/pe reads across the warp).
// ---------------------------------------------------------------------------
__global__ __launch_bounds__(320) void diag_kernel(
    const int*   __restrict__ x1,
    const int*   __restrict__ x2,
    const float* __restrict__ emb1,
    const float* __restrict__ emb2)
{
    const int i   = blockIdx.x;     // diag index == batch index, 0..299
    const int tid = threadIdx.x;
    const float scale = 17.320508075688775f;  // sqrt(300)

    __shared__ float s[LSEQ];
    __shared__ int   r1[LSEQ];      // emb1 row byte-offsets (element offset)

    for (int l = tid; l < LSEQ; l += 320) {
        int t2 = x2[i * LSEQ + l];
        s[l]  = fmaf(emb2[t2 * D + i], scale, g_pe[l * D + i]);
        r1[l] = x1[i * LSEQ + l] * D;
    }
    __syncthreads();

    if (tid < D) {
        const int e = tid;
        const float* pe_e = g_pe + e;
        float acc[4] = {0.f, 0.f, 0.f, 0.f};
        #pragma unroll 4
        for (int l = 0; l < LSEQ; l += 4) {
            #pragma unroll
            for (int u = 0; u < 4; ++u) {
                float v = fmaf(emb1[r1[l + u] + e], scale, pe_e[(l + u) * D]);
                acc[u] = fmaf(s[l + u], v, acc[u]);
            }
        }
        g_diag[e * D + i] = (acc[0] + acc[1]) + (acc[2] + acc[3]);
    }
}

// ---------------------------------------------------------------------------
// Kernel 2: FC1(relu) -> FC2 -> softmax, 8 e-rows per block.
//   h[e,j]     = relu(sum_i diag[e,i] * w1[j,i] + b1[j])
//   logits[e,o]= sum_j h[e,j] * w2[o,j] + b2[o]
//   out[e,:]   = softmax(logits[e,:])
// ---------------------------------------------------------------------------
#define EPB 8
__global__ __launch_bounds__(128) void fc_kernel(
    const float* __restrict__ w1,
    const float* __restrict__ b1,
    const float* __restrict__ w2,
    const float* __restrict__ b2,
    float*       __restrict__ out)
{
    __shared__ float sd[EPB][D];   // diag rows for this block
    __shared__ float sh[EPB][D];   // hidden rows

    const int e0  = blockIdx.x * EPB;
    const int tid = threadIdx.x;

    for (int idx = tid; idx < EPB * D; idx += 128) {
        int ee = idx / D, ii = idx % D;
        int e  = e0 + ee;
        sd[ee][ii] = (e < D) ? g_diag[e * D + ii] : 0.f;
    }
    __syncthreads();

    for (int j = tid; j < D; j += 128) {
        float acc[EPB];
        #pragma unroll
        for (int u = 0; u < EPB; ++u) acc[u] = 0.f;
        const float* w1r = w1 + j * D;
        for (int ii = 0; ii < D; ++ii) {
            float w = w1r[ii];
            #pragma unroll
            for (int u = 0; u < EPB; ++u) acc[u] = fmaf(w, sd[u][ii], acc[u]);
        }
        float bb = b1[j];
        #pragma unroll
        for (int u = 0; u < EPB; ++u) sh[u][j] = fmaxf(acc[u] + bb, 0.f);
    }
    __syncthreads();

    // One thread per e-row: 4 logits (300-term dots), softmax, store.
    if (tid < EPB && (e0 + tid) < D) {
        const int e = e0 + tid;
        float logits[OUTC];
        #pragma unroll
        for (int o = 0; o < OUTC; ++o) {
            const float* w2r = w2 + o * D;
            float a = 0.f;
            for (int j = 0; j < D; ++j) a = fmaf(sh[tid][j], w2r[j], a);
            logits[o] = a + b2[o];
        }
        float m = fmaxf(fmaxf(logits[0], logits[1]), fmaxf(logits[2], logits[3]));
        float es[OUTC], ssum = 0.f;
        #pragma unroll
        for (int o = 0; o < OUTC; ++o) { es[o] = expf(logits[o] - m); ssum += es[o]; }
        float inv = 1.f / ssum;
        #pragma unroll
        for (int o = 0; o < OUTC; ++o) out[e * OUTC + o] = es[o] * inv;
    }
}

// ---------------------------------------------------------------------------
// Launch
// Inputs (metadata order): x1[512*512] i32, x2[512*512] i32,
//   emb1[32000*300] f32, emb2[32000*300] f32, w1[300*300] f32, b1[300] f32,
//   w2[4*300] f32, b2[4] f32.  Output: f32[300*4].
// ---------------------------------------------------------------------------
extern "C" void kernel_launch(void* const* d_in, const int* in_sizes, int n_in,
                              void* d_out, int out_size) {
    const int*   x1   = (const int*)  d_in[0];
    const int*   x2   = (const int*)  d_in[1];
    const float* emb1 = (const float*)d_in[2];
    const float* emb2 = (const float*)d_in[3];
    const float* w1   = (const float*)d_in[4];
    const float* b1   = (const float*)d_in[5];
    const float* w2   = (const float*)d_in[6];
    const float* b2   = (const float*)d_in[7];
    float* out = (float*)d_out;

    pe_kernel<<<(LSEQ * D + 255) / 256, 256>>>();
    diag_kernel<<<D, 320>>>(x1, x2, emb1, emb2);
    fc_kernel<<<(D + EPB - 1) / EPB, 128>>>(w1, b1, w2, b2, out);
}

// round 2
// speedup vs baseline: 1.0368x; 1.0368x over previous
#include <cuda_runtime.h>
#include <math.h>

// D_MODEL=300, L=512, B=512, OUT=4.
// diag[e,i] = fmap[i,i,e] = sum_l e2[i,l,i] * e1[i,l,e], i in [0,300)
// Split:  diag[e,i] = scale * sum_l s[i,l]*emb1[x1[i,l]][e]      (term1, gather)
//                   +          sum_l s[i,l]*pe[l][e]             (term2, dense GEMM)
// with    s[i,l] = emb2[x2[i,l]][i]*scale + pe[l][i]

#define D     300
#define LSEQ  512
#define OUTC  4
#define NCH   4
#define CHUNK 128   // LSEQ / NCH

__device__ float g_pe[LSEQ * D];          // [l][d]
__device__ float g_s[D * LSEQ];           // [i][l]
__device__ float g_part[NCH * D * D];     // [chunk][i][e]  (term1 partials, unscaled)
__device__ float g_diag[D * D];           // [e][i]

// ---------------------------------------------------------------------------
// Kernel 0: positional encoding, float32 throughout (matches jnp float32 path).
// ---------------------------------------------------------------------------
__global__ void pe_kernel() {
    int idx = blockIdx.x * blockDim.x + threadIdx.x;
    if (idx >= LSEQ * D) return;
    int l = idx / D;
    int d = idx % D;
    int k = d >> 1;
    const float coef = -9.210340371976184f / (float)D;   // -ln(10000)/300
    float divv = expf((float)(2 * k) * coef);
    float ang  = (float)l * divv;
    g_pe[idx] = (d & 1) ? cosf(ang) : sinf(ang);
}

// ---------------------------------------------------------------------------
// Kernel 1: term1 partials. One block per (i, l-chunk).
// Phase A (tid<CHUNK): compute s[i,l] (emb2 gather + pe), store smem + g_s,
//                      and stage emb1 row offsets.
// Phase B (tid<D):     part[chunk][i][e] = sum_{l in chunk} s[l] * emb1[row_l][e]
// ---------------------------------------------------------------------------
__global__ __launch_bounds__(320) void term1_kernel(
    const int*   __restrict__ x1,
    const int*   __restrict__ x2,
    const float* __restrict__ emb1,
    const float* __restrict__ emb2)
{
    const int chunk = blockIdx.x;          // 0..3
    const int i     = blockIdx.y;          // 0..299
    const int tid   = threadIdx.x;
    const float scale = 17.320508075688775f;  // sqrt(300)

    __shared__ float s_sh[CHUNK];
    __shared__ int   r1_sh[CHUNK];

    if (tid < CHUNK) {
        int l  = chunk * CHUNK + tid;
        int t2 = x2[i * LSEQ + l];
        float sv = fmaf(emb2[t2 * D + i], scale, g_pe[l * D + i]);
        s_sh[tid] = sv;
        g_s[i * LSEQ + l] = sv;
        r1_sh[tid] = x1[i * LSEQ + l] * D;
    }
    __syncthreads();

    if (tid < D) {
        const int e = tid;
        float acc[8];
        #pragma unroll
        for (int u = 0; u < 8; ++u) acc[u] = 0.f;
        #pragma unroll 2
        for (int l = 0; l < CHUNK; l += 8) {
            #pragma unroll
            for (int u = 0; u < 8; ++u)
                acc[u] = fmaf(s_sh[l + u], emb1[r1_sh[l + u] + e], acc[u]);
        }
        float r = ((acc[0] + acc[1]) + (acc[2] + acc[3]))
                + ((acc[4] + acc[5]) + (acc[6] + acc[7]));
        g_part[(chunk * D + i) * D + e] = r;
    }
}

// ---------------------------------------------------------------------------
// Kernel 2: term2 GEMM (S[300x512] x PE[512x300]) + partial reduction.
//   g_diag[e][i] = scale*(sum_c part[c][i][e]) + sum_l s[i,l]*pe[l][e]
// Tiles 32x32, K-step 32. blockDim (32,8), 4 outputs/thread along i.
// ---------------------------------------------------------------------------
__global__ __launch_bounds__(256) void combine_kernel()
{
    __shared__ float sh_s[32][33];    // [i_local][k_local]
    __shared__ float sh_pe[32][33];   // [k_local][e_local]

    const int tx = threadIdx.x;       // 0..31  -> e
    const int ty = threadIdx.y;       // 0..7   -> i (x4)
    const int e0 = blockIdx.x * 32;
    const int i0 = blockIdx.y * 32;
    const int lin = ty * 32 + tx;     // 0..255

    const float scale = 17.320508075688775f;

    float acc[4] = {0.f, 0.f, 0.f, 0.f};

    for (int k0 = 0; k0 < LSEQ; k0 += 32) {
        // load s tile: rows i0..i0+31, cols k0..k0+31
        #pragma unroll
        for (int t = 0; t < 4; ++t) {
            int idx = lin + t * 256;          // 0..1023
            int row = idx >> 5, col = idx & 31;
            int ii = i0 + row;
            sh_s[row][col] = (ii < D) ? g_s[ii * LSEQ + k0 + col] : 0.f;
        }
        // load pe tile: rows k0..k0+31, cols e0..e0+31
        #pragma unroll
        for (int t = 0; t < 4; ++t) {
            int idx = lin + t * 256;
            int row = idx >> 5, col = idx & 31;
            int ee = e0 + col;
            sh_pe[row][col] = (ee < D) ? g_pe[(k0 + row) * D + ee] : 0.f;
        }
        __syncthreads();

        #pragma unroll
        for (int kk = 0; kk < 32; ++kk) {
            float pv = sh_pe[kk][tx];
            #pragma unroll
            for (int u = 0; u < 4; ++u)
                acc[u] = fmaf(sh_s[ty + 8 * u][kk], pv, acc[u]);
        }
        __syncthreads();
    }

    const int e = e0 + tx;
    if (e < D) {
        #pragma unroll
        for (int u = 0; u < 4; ++u) {
            int i = i0 + ty + 8 * u;
            if (i < D) {
                float p = g_part[(0 * D + i) * D + e]
                        + g_part[(1 * D + i) * D + e]
                        + g_part[(2 * D + i) * D + e]
                        + g_part[(3 * D + i) * D + e];
                g_diag[e * D + i] = fmaf(scale, p, acc[u]);
            }
        }
    }
}

// ---------------------------------------------------------------------------
// Kernel 3: FC1(relu) -> FC2 -> softmax, 8 e-rows per block.
// ---------------------------------------------------------------------------
#define EPB 8
__global__ __launch_bounds__(128) void fc_kernel(
    const float* __restrict__ w1,
    const float* __restrict__ b1,
    const float* __restrict__ w2,
    const float* __restrict__ b2,
    float*       __restrict__ out)
{
    __shared__ float sd[EPB][D];
    __shared__ float sh[EPB][D];

    const int e0  = blockIdx.x * EPB;
    const int tid = threadIdx.x;

    for (int idx = tid; idx < EPB * D; idx += 128) {
        int ee = idx / D, ii = idx % D;
        int e  = e0 + ee;
        sd[ee][ii] = (e < D) ? g_diag[e * D + ii] : 0.f;
    }
    __syncthreads();

    for (int j = tid; j < D; j += 128) {
        float acc[EPB];
        #pragma unroll
        for (int u = 0; u < EPB; ++u) acc[u] = 0.f;
        const float* w1r = w1 + j * D;
        for (int ii = 0; ii < D; ++ii) {
            float w = w1r[ii];
            #pragma unroll
            for (int u = 0; u < EPB; ++u) acc[u] = fmaf(w, sd[u][ii], acc[u]);
        }
        float bb = b1[j];
        #pragma unroll
        for (int u = 0; u < EPB; ++u) sh[u][j] = fmaxf(acc[u] + bb, 0.f);
    }
    __syncthreads();

    if (tid < EPB && (e0 + tid) < D) {
        const int e = e0 + tid;
        float logits[OUTC];
        #pragma unroll
        for (int o = 0; o < OUTC; ++o) {
            const float* w2r = w2 + o * D;
            float a = 0.f;
            for (int j = 0; j < D; ++j) a = fmaf(sh[tid][j], w2r[j], a);
            logits[o] = a + b2[o];
        }
        float m = fmaxf(fmaxf(logits[0], logits[1]), fmaxf(logits[2], logits[3]));
        float es[OUTC], ssum = 0.f;
        #pragma unroll
        for (int o = 0; o < OUTC; ++o) { es[o] = expf(logits[o] - m); ssum += es[o]; }
        float inv = 1.f / ssum;
        #pragma unroll
        for (int o = 0; o < OUTC; ++o) out[e * OUTC + o] = es[o] * inv;
    }
}

// ---------------------------------------------------------------------------
// Launch. Inputs: x1, x2 (i32 [512*512]); emb1, emb2 (f32 [32000*300]);
// w1 (f32 [300*300]); b1 (f32 [300]); w2 (f32 [4*300]); b2 (f32 [4]).
// Output: f32 [300*4].
// ---------------------------------------------------------------------------
extern "C" void kernel_launch(void* const* d_in, const int* in_sizes, int n_in,
                              void* d_out, int out_size) {
    const int*   x1   = (const int*)  d_in[0];
    const int*   x2   = (const int*)  d_in[1];
    const float* emb1 = (const float*)d_in[2];
    const float* emb2 = (const float*)d_in[3];
    const float* w1   = (const float*)d_in[4];
    const float* b1   = (const float*)d_in[5];
    const float* w2   = (const float*)d_in[6];
    const float* b2   = (const float*)d_in[7];
    float* out = (float*)d_out;

    pe_kernel<<<(LSEQ * D + 255) / 256, 256>>>();
    dim3 g1(NCH, D);
    term1_kernel<<<g1, 320>>>(x1, x2, emb1, emb2);
    dim3 g2(10, 10);  // ceil(300/32) x ceil(300/32)
    combine_kernel<<<g2, dim3(32, 8)>>>();
    fc_kernel<<<(D + EPB - 1) / EPB, 128>>>(w1, b1, w2, b2, out);
}

// round 3
// speedup vs baseline: 1.8929x; 1.8256x over previous
#include <cuda_runtime.h>
#include <math.h>

// D_MODEL=300, L=512, B=512, OUT=4.
// diag[e,i] = fmap[i,i,e] = sum_l e2[i,l,i] * e1[i,l,e], i in [0,300)
// Split:  diag[e,i] = scale * sum_l s[i,l]*emb1[x1[i,l]][e]      (term1, gather)
//                   +          sum_l s[i,l]*pe[l][e]             (term2, dense GEMM)
// with    s[i,l] = emb2[x2[i,l]][i]*scale + pe[l][i]

#define D     300
#define LSEQ  512
#define OUTC  4
#define NCH   4
#define CHUNK 128   // LSEQ / NCH

__device__ float g_pe[LSEQ * D];          // [l][d]
__device__ float g_s[D * LSEQ];           // [i][l]
__device__ float g_part[NCH * D * D];     // [chunk][i][e]
__device__ float g_diag[D * D];           // [e][i]
__device__ float g_h[D * D];              // hidden [e][j]

// ---------------------------------------------------------------------------
// Kernel 0: positional encoding, float32 (matches jnp float32 path).
// ---------------------------------------------------------------------------
__global__ void pe_kernel() {
    int idx = blockIdx.x * blockDim.x + threadIdx.x;
    if (idx >= LSEQ * D) return;
    int l = idx / D;
    int d = idx % D;
    int k = d >> 1;
    const float coef = -9.210340371976184f / (float)D;   // -ln(10000)/300
    float divv = expf((float)(2 * k) * coef);
    float ang  = (float)l * divv;
    g_pe[idx] = (d & 1) ? cosf(ang) : sinf(ang);
}

// ---------------------------------------------------------------------------
// Kernel 1: term1 partials. One block per (i, l-chunk).
// ---------------------------------------------------------------------------
__global__ __launch_bounds__(320) void term1_kernel(
    const int*   __restrict__ x1,
    const int*   __restrict__ x2,
    const float* __restrict__ emb1,
    const float* __restrict__ emb2)
{
    const int chunk = blockIdx.x;          // 0..3
    const int i     = blockIdx.y;          // 0..299
    const int tid   = threadIdx.x;
    const float scale = 17.320508075688775f;  // sqrt(300)

    __shared__ float s_sh[CHUNK];
    __shared__ int   r1_sh[CHUNK];

    if (tid < CHUNK) {
        int l  = chunk * CHUNK + tid;
        int t2 = x2[i * LSEQ + l];
        float sv = fmaf(emb2[t2 * D + i], scale, g_pe[l * D + i]);
        s_sh[tid] = sv;
        g_s[i * LSEQ + l] = sv;
        r1_sh[tid] = x1[i * LSEQ + l] * D;
    }
    __syncthreads();

    if (tid < D) {
        const int e = tid;
        float acc[8];
        #pragma unroll
        for (int u = 0; u < 8; ++u) acc[u] = 0.f;
        #pragma unroll 2
        for (int l = 0; l < CHUNK; l += 8) {
            #pragma unroll
            for (int u = 0; u < 8; ++u)
                acc[u] = fmaf(s_sh[l + u], emb1[r1_sh[l + u] + e], acc[u]);
        }
        float r = ((acc[0] + acc[1]) + (acc[2] + acc[3]))
                + ((acc[4] + acc[5]) + (acc[6] + acc[7]));
        g_part[(chunk * D + i) * D + e] = r;
    }
}

// ---------------------------------------------------------------------------
// Kernel 2: term2 GEMM (S[300x512] x PE[512x300]) + partial reduction.
//   g_diag[e][i] = scale*(sum_c part[c][i][e]) + sum_l s[i,l]*pe[l][e]
// ---------------------------------------------------------------------------
__global__ __launch_bounds__(256) void combine_kernel()
{
    __shared__ float sh_s[32][33];    // [i_local][k_local]
    __shared__ float sh_pe[32][33];   // [k_local][e_local]

    const int tx = threadIdx.x;       // 0..31  -> e
    const int ty = threadIdx.y;       // 0..7   -> i (x4)
    const int e0 = blockIdx.x * 32;
    const int i0 = blockIdx.y * 32;
    const int lin = ty * 32 + tx;

    const float scale = 17.320508075688775f;

    float acc[4] = {0.f, 0.f, 0.f, 0.f};

    for (int k0 = 0; k0 < LSEQ; k0 += 32) {
        #pragma unroll
        for (int t = 0; t < 4; ++t) {
            int idx = lin + t * 256;
            int row = idx >> 5, col = idx & 31;
            int ii = i0 + row;
            sh_s[row][col] = (ii < D) ? g_s[ii * LSEQ + k0 + col] : 0.f;
        }
        #pragma unroll
        for (int t = 0; t < 4; ++t) {
            int idx = lin + t * 256;
            int row = idx >> 5, col = idx & 31;
            int ee = e0 + col;
            sh_pe[row][col] = (ee < D) ? g_pe[(k0 + row) * D + ee] : 0.f;
        }
        __syncthreads();

        #pragma unroll
        for (int kk = 0; kk < 32; ++kk) {
            float pv = sh_pe[kk][tx];
            #pragma unroll
            for (int u = 0; u < 4; ++u)
                acc[u] = fmaf(sh_s[ty + 8 * u][kk], pv, acc[u]);
        }
        __syncthreads();
    }

    const int e = e0 + tx;
    if (e < D) {
        #pragma unroll
        for (int u = 0; u < 4; ++u) {
            int i = i0 + ty + 8 * u;
            if (i < D) {
                float p = g_part[(0 * D + i) * D + e]
                        + g_part[(1 * D + i) * D + e]
                        + g_part[(2 * D + i) * D + e]
                        + g_part[(3 * D + i) * D + e];
                g_diag[e * D + i] = fmaf(scale, p, acc[u]);
            }
        }
    }
}

// ---------------------------------------------------------------------------
// Kernel 3: FC1 as tiled GEMM:  H[e][j] = relu(sum_i diag[e][i]*w1[j][i] + b1[j])
// Both operands are i-contiguous (A.Bt tiling). 32x32 tiles, K-step 32.
// blockDim (32,8): tx -> j, ty(+8u) -> e.
// ---------------------------------------------------------------------------
__global__ __launch_bounds__(256) void fc1_kernel(
    const float* __restrict__ w1,
    const float* __restrict__ b1)
{
    __shared__ float sh_a[32][33];    // diag tile [e_local][k_local]
    __shared__ float sh_b[32][33];    // w1   tile [j_local][k_local]

    const int tx = threadIdx.x;       // 0..31 -> j
    const int ty = threadIdx.y;       // 0..7  -> e (x4)
    const int j0 = blockIdx.x * 32;
    const int e0 = blockIdx.y * 32;
    const int lin = ty * 32 + tx;

    float acc[4] = {0.f, 0.f, 0.f, 0.f};

    for (int k0 = 0; k0 < D; k0 += 32) {
        #pragma unroll
        for (int t = 0; t < 4; ++t) {
            int idx = lin + t * 256;
            int row = idx >> 5, col = idx & 31;
            int ee = e0 + row, kk = k0 + col;
            sh_a[row][col] = (ee < D && kk < D) ? g_diag[ee * D + kk] : 0.f;
        }
        #pragma unroll
        for (int t = 0; t < 4; ++t) {
            int idx = lin + t * 256;
            int row = idx >> 5, col = idx & 31;
            int jj = j0 + row, kk = k0 + col;
            sh_b[row][col] = (jj < D && kk < D) ? w1[jj * D + kk] : 0.f;
        }
        __syncthreads();

        #pragma unroll
        for (int kk = 0; kk < 32; ++kk) {
            float bv = sh_b[tx][kk];
            #pragma unroll
            for (int u = 0; u < 4; ++u)
                acc[u] = fmaf(sh_a[ty + 8 * u][kk], bv, acc[u]);
        }
        __syncthreads();
    }

    const int j = j0 + tx;
    if (j < D) {
        float bb = b1[j];
        #pragma unroll
        for (int u = 0; u < 4; ++u) {
            int e = e0 + ty + 8 * u;
            if (e < D) g_h[e * D + j] = fmaxf(acc[u] + bb, 0.f);
        }
    }
}

// ---------------------------------------------------------------------------
// Kernel 4: FC2 + softmax. One block per e-row, 128 threads reduce the 4
// logits in parallel.
// ---------------------------------------------------------------------------
__global__ __launch_bounds__(128) void fc2_kernel(
    const float* __restrict__ w2,
    const float* __restrict__ b2,
    float*       __restrict__ out)
{
    const int e   = blockIdx.x;
    const int tid = threadIdx.x;

    float p[OUTC] = {0.f, 0.f, 0.f, 0.f};
    for (int j = tid; j < D; j += 128) {
        float hv = g_h[e * D + j];
        #pragma unroll
        for (int o = 0; o < OUTC; ++o)
            p[o] = fmaf(hv, w2[o * D + j], p[o]);
    }

    // warp reduce
    #pragma unroll
    for (int off = 16; off > 0; off >>= 1) {
        #pragma unroll
        for (int o = 0; o < OUTC; ++o)
            p[o] += __shfl_xor_sync(0xFFFFFFFFu, p[o], off);
    }

    __shared__ float red[4][OUTC];
    const int wid = tid >> 5, lid = tid & 31;
    if (lid == 0) {
        #pragma unroll
        for (int o = 0; o < OUTC; ++o) red[wid][o] = p[o];
    }
    __syncthreads();

    if (tid == 0) {
        float logits[OUTC];
        #pragma unroll
        for (int o = 0; o < OUTC; ++o)
            logits[o] = red[0][o] + red[1][o] + red[2][o] + red[3][o] + b2[o];
        float m = fmaxf(fmaxf(logits[0], logits[1]), fmaxf(logits[2], logits[3]));
        float es[OUTC], ssum = 0.f;
        #pragma unroll
        for (int o = 0; o < OUTC; ++o) { es[o] = expf(logits[o] - m); ssum += es[o]; }
        float inv = 1.f / ssum;
        #pragma unroll
        for (int o = 0; o < OUTC; ++o) out[e * OUTC + o] = es[o] * inv;
    }
}

// ---------------------------------------------------------------------------
// Launch. Inputs: x1, x2 (i32 [512*512]); emb1, emb2 (f32 [32000*300]);
// w1 (f32 [300*300]); b1 (f32 [300]); w2 (f32 [4*300]); b2 (f32 [4]).
// Output: f32 [300*4].
// ---------------------------------------------------------------------------
extern "C" void kernel_launch(void* const* d_in, const int* in_sizes, int n_in,
                              void* d_out, int out_size) {
    const int*   x1   = (const int*)  d_in[0];
    const int*   x2   = (const int*)  d_in[1];
    const float* emb1 = (const float*)d_in[2];
    const float* emb2 = (const float*)d_in[3];
    const float* w1   = (const float*)d_in[4];
    const float* b1   = (const float*)d_in[5];
    const float* w2   = (const float*)d_in[6];
    const float* b2   = (const float*)d_in[7];
    float* out = (float*)d_out;

    pe_kernel<<<(LSEQ * D + 255) / 256, 256>>>();
    dim3 g1(NCH, D);
    term1_kernel<<<g1, 320>>>(x1, x2, emb1, emb2);
    dim3 g2(10, 10);
    combine_kernel<<<g2, dim3(32, 8)>>>();
    fc1_kernel<<<dim3(10, 10), dim3(32, 8)>>>(w1, b1);
    fc2_kernel<<<D, 128>>>(w2, b2, out);
}

// round 4
// speedup vs baseline: 1.9542x; 1.0324x over previous
#include <cuda_runtime.h>
#include <math.h>

// D_MODEL=300, L=512, B=512, OUT=4.
// diag[e,i] = fmap[i,i,e] = sum_l e2[i,l,i] * e1[i,l,e], i in [0,300)
// Split:  diag[e,i] = scale * sum_l s[i,l]*emb1[x1[i,l]][e]      (term1, gather)
//                   +          sum_l s[i,l]*pe[l][e]             (term2, dense GEMM)
// with    s[i,l] = emb2[x2[i,l]][i]*scale + pe[l][i]

#define D     300
#define LSEQ  512
#define OUTC  4
#define NCH   4
#define CHUNK 128   // LSEQ / NCH

__device__ float g_pe[LSEQ * D];          // [l][d]
__device__ float g_s[D * LSEQ];           // [i][l]
__device__ float g_part[NCH * D * D];     // [chunk][i][e]
__device__ float g_diag[D * D];           // [e][i]
__device__ float g_h[D * D];              // hidden [e][j]

// ---------------------------------------------------------------------------
// Kernel 0: positional encoding, float32 (matches jnp float32 path).
// ---------------------------------------------------------------------------
__global__ void pe_kernel() {
    int idx = blockIdx.x * blockDim.x + threadIdx.x;
    if (idx >= LSEQ * D) return;
    int l = idx / D;
    int d = idx % D;
    int k = d >> 1;
    const float coef = -9.210340371976184f / (float)D;   // -ln(10000)/300
    float divv = expf((float)(2 * k) * coef);
    float ang  = (float)l * divv;
    g_pe[idx] = (d & 1) ? cosf(ang) : sinf(ang);
}

// ---------------------------------------------------------------------------
// Kernel 1: term1 partials. One block per (i, l-chunk).
// ---------------------------------------------------------------------------
__global__ __launch_bounds__(320) void term1_kernel(
    const int*   __restrict__ x1,
    const int*   __restrict__ x2,
    const float* __restrict__ emb1,
    const float* __restrict__ emb2)
{
    const int chunk = blockIdx.x;          // 0..3
    const int i     = blockIdx.y;          // 0..299
    const int tid   = threadIdx.x;
    const float scale = 17.320508075688775f;  // sqrt(300)

    __shared__ float s_sh[CHUNK];
    __shared__ int   r1_sh[CHUNK];

    if (tid < CHUNK) {
        int l  = chunk * CHUNK + tid;
        int t2 = x2[i * LSEQ + l];
        float sv = fmaf(emb2[t2 * D + i], scale, g_pe[l * D + i]);
        s_sh[tid] = sv;
        g_s[i * LSEQ + l] = sv;
        r1_sh[tid] = x1[i * LSEQ + l] * D;
    }
    __syncthreads();

    if (tid < D) {
        const int e = tid;
        float acc[8];
        #pragma unroll
        for (int u = 0; u < 8; ++u) acc[u] = 0.f;
        #pragma unroll 2
        for (int l = 0; l < CHUNK; l += 8) {
            #pragma unroll
            for (int u = 0; u < 8; ++u)
                acc[u] = fmaf(s_sh[l + u], emb1[r1_sh[l + u] + e], acc[u]);
        }
        float r = ((acc[0] + acc[1]) + (acc[2] + acc[3]))
                + ((acc[4] + acc[5]) + (acc[6] + acc[7]));
        g_part[(chunk * D + i) * D + e] = r;
    }
}

// ---------------------------------------------------------------------------
// Kernel 2: term2 GEMM (S[300x512] x PE[512x300]) + partial reduction.
//   g_diag[e][i] = scale*(sum_c part[c][i][e]) + sum_l s[i,l]*pe[l][e]
// ---------------------------------------------------------------------------
__global__ __launch_bounds__(256) void combine_kernel()
{
    __shared__ float sh_s[32][33];    // [i_local][k_local]
    __shared__ float sh_pe[32][33];   // [k_local][e_local]

    const int tx = threadIdx.x;       // 0..31  -> e
    const int ty = threadIdx.y;       // 0..7   -> i (x4)
    const int e0 = blockIdx.x * 32;
    const int i0 = blockIdx.y * 32;
    const int lin = ty * 32 + tx;

    const float scale = 17.320508075688775f;

    float acc[4] = {0.f, 0.f, 0.f, 0.f};

    for (int k0 = 0; k0 < LSEQ; k0 += 32) {
        #pragma unroll
        for (int t = 0; t < 4; ++t) {
            int idx = lin + t * 256;
            int row = idx >> 5, col = idx & 31;
            int ii = i0 + row;
            sh_s[row][col] = (ii < D) ? g_s[ii * LSEQ + k0 + col] : 0.f;
        }
        #pragma unroll
        for (int t = 0; t < 4; ++t) {
            int idx = lin + t * 256;
            int row = idx >> 5, col = idx & 31;
            int ee = e0 + col;
            sh_pe[row][col] = (ee < D) ? g_pe[(k0 + row) * D + ee] : 0.f;
        }
        __syncthreads();

        #pragma unroll
        for (int kk = 0; kk < 32; ++kk) {
            float pv = sh_pe[kk][tx];
            #pragma unroll
            for (int u = 0; u < 4; ++u)
                acc[u] = fmaf(sh_s[ty + 8 * u][kk], pv, acc[u]);
        }
        __syncthreads();
    }

    const int e = e0 + tx;
    if (e < D) {
        #pragma unroll
        for (int u = 0; u < 4; ++u) {
            int i = i0 + ty + 8 * u;
            if (i < D) {
                float p = g_part[(0 * D + i) * D + e]
                        + g_part[(1 * D + i) * D + e]
                        + g_part[(2 * D + i) * D + e]
                        + g_part[(3 * D + i) * D + e];
                g_diag[e * D + i] = fmaf(scale, p, acc[u]);
            }
        }
    }
}

// ---------------------------------------------------------------------------
// Kernel 3: FC1:  H[e][j] = relu(sum_i diag[e][i]*w1[j][i] + b1[j])
// 128 threads (16,8), 32x32 output tile, 2j x 4e register tile per thread,
// K staged in 2 tiles of 152 (smem ~39 KB, only 4 barriers total).
// ---------------------------------------------------------------------------
#define KT 152
__global__ __launch_bounds__(128) void fc1_kernel(
    const float* __restrict__ w1,
    const float* __restrict__ b1)
{
    __shared__ float sa[32][KT + 1];   // diag tile [e][k], stride 153 (odd)
    __shared__ float sb[32][KT + 1];   // w1   tile [j][k]

    const int tx  = threadIdx.x;       // 0..15 -> j base
    const int ty  = threadIdx.y;       // 0..7  -> e base
    const int lin = ty * 16 + tx;
    const int j0  = blockIdx.x * 32;
    const int e0  = blockIdx.y * 32;

    float acc[2][4];
    #pragma unroll
    for (int jj = 0; jj < 2; ++jj)
        #pragma unroll
        for (int u = 0; u < 4; ++u) acc[jj][u] = 0.f;

    #pragma unroll
    for (int kt = 0; kt < 2; ++kt) {
        const int kb = kt * KT;
        // Stage tiles: float4 global loads, scalar smem stores.
        for (int idx = lin; idx < 32 * (KT / 4); idx += 128) {
            int row = idx / (KT / 4);          // 0..31
            int c4  = idx % (KT / 4);          // 0..37
            int k   = kb + c4 * 4;
            float4 va = make_float4(0.f, 0.f, 0.f, 0.f);
            float4 vb = va;
            if (k < D) {                       // k%4==0, D%4==0 -> whole vec valid
                if (e0 + row < D)
                    va = *reinterpret_cast<const float4*>(g_diag + (e0 + row) * D + k);
                if (j0 + row < D)
                    vb = *reinterpret_cast<const float4*>(w1 + (j0 + row) * D + k);
            }
            int cc = c4 * 4;
            sa[row][cc] = va.x; sa[row][cc + 1] = va.y;
            sa[row][cc + 2] = va.z; sa[row][cc + 3] = va.w;
            sb[row][cc] = vb.x; sb[row][cc + 1] = vb.y;
            sb[row][cc + 2] = vb.z; sb[row][cc + 3] = vb.w;
        }
        __syncthreads();

        #pragma unroll 4
        for (int k = 0; k < KT; ++k) {
            float b0 = sb[tx][k];
            float b1v = sb[tx + 16][k];
            float a0 = sa[ty][k];
            float a1 = sa[ty + 8][k];
            float a2 = sa[ty + 16][k];
            float a3 = sa[ty + 24][k];
            acc[0][0] = fmaf(b0, a0, acc[0][0]);
            acc[0][1] = fmaf(b0, a1, acc[0][1]);
            acc[0][2] = fmaf(b0, a2, acc[0][2]);
            acc[0][3] = fmaf(b0, a3, acc[0][3]);
            acc[1][0] = fmaf(b1v, a0, acc[1][0]);
            acc[1][1] = fmaf(b1v, a1, acc[1][1]);
            acc[1][2] = fmaf(b1v, a2, acc[1][2]);
            acc[1][3] = fmaf(b1v, a3, acc[1][3]);
        }
        __syncthreads();
    }

    #pragma unroll
    for (int jj = 0; jj < 2; ++jj) {
        int j = j0 + tx + 16 * jj;
        if (j < D) {
            float bb = b1[j];
            #pragma unroll
            for (int u = 0; u < 4; ++u) {
                int e = e0 + ty + 8 * u;
                if (e < D) g_h[e * D + j] = fmaxf(acc[jj][u] + bb, 0.f);
            }
        }
    }
}

// ---------------------------------------------------------------------------
// Kernel 4: FC2 + softmax. One block per e-row.
// ---------------------------------------------------------------------------
__global__ __launch_bounds__(128) void fc2_kernel(
    const float* __restrict__ w2,
    const float* __restrict__ b2,
    float*       __restrict__ out)
{
    const int e   = blockIdx.x;
    const int tid = threadIdx.x;

    float p[OUTC] = {0.f, 0.f, 0.f, 0.f};
    for (int j = tid; j < D; j += 128) {
        float hv = g_h[e * D + j];
        #pragma unroll
        for (int o = 0; o < OUTC; ++o)
            p[o] = fmaf(hv, w2[o * D + j], p[o]);
    }

    #pragma unroll
    for (int off = 16; off > 0; off >>= 1) {
        #pragma unroll
        for (int o = 0; o < OUTC; ++o)
            p[o] += __shfl_xor_sync(0xFFFFFFFFu, p[o], off);
    }

    __shared__ float red[4][OUTC];
    const int wid = tid >> 5, lid = tid & 31;
    if (lid == 0) {
        #pragma unroll
        for (int o = 0; o < OUTC; ++o) red[wid][o] = p[o];
    }
    __syncthreads();

    if (tid == 0) {
        float logits[OUTC];
        #pragma unroll
        for (int o = 0; o < OUTC; ++o)
            logits[o] = red[0][o] + red[1][o] + red[2][o] + red[3][o] + b2[o];
        float m = fmaxf(fmaxf(logits[0], logits[1]), fmaxf(logits[2], logits[3]));
        float es[OUTC], ssum = 0.f;
        #pragma unroll
        for (int o = 0; o < OUTC; ++o) { es[o] = expf(logits[o] - m); ssum += es[o]; }
        float inv = 1.f / ssum;
        #pragma unroll
        for (int o = 0; o < OUTC; ++o) out[e * OUTC + o] = es[o] * inv;
    }
}

// ---------------------------------------------------------------------------
// Launch. Inputs: x1, x2 (i32 [512*512]); emb1, emb2 (f32 [32000*300]);
// w1 (f32 [300*300]); b1 (f32 [300]); w2 (f32 [4*300]); b2 (f32 [4]).
// Output: f32 [300*4].
// ---------------------------------------------------------------------------
extern "C" void kernel_launch(void* const* d_in, const int* in_sizes, int n_in,
                              void* d_out, int out_size) {
    const int*   x1   = (const int*)  d_in[0];
    const int*   x2   = (const int*)  d_in[1];
    const float* emb1 = (const float*)d_in[2];
    const float* emb2 = (const float*)d_in[3];
    const float* w1   = (const float*)d_in[4];
    const float* b1   = (const float*)d_in[5];
    const float* w2   = (const float*)d_in[6];
    const float* b2   = (const float*)d_in[7];
    float* out = (float*)d_out;

    pe_kernel<<<(LSEQ * D + 255) / 256, 256>>>();
    dim3 g1(NCH, D);
    term1_kernel<<<g1, 320>>>(x1, x2, emb1, emb2);
    dim3 g2(10, 10);
    combine_kernel<<<g2, dim3(32, 8)>>>();
    fc1_kernel<<<dim3(10, 10), dim3(16, 8)>>>(w1, b1);
    fc2_kernel<<<D, 128>>>(w2, b2, out);
}

// round 5
// speedup vs baseline: 2.5531x; 1.3065x over previous
#include <cuda_runtime.h>
#include <math.h>

// D_MODEL=300, L=512, B=512, OUT=4.
// diag[e,i] = fmap[i,i,e] = sum_l e2[i,l,i] * e1[i,l,e], i in [0,300)
// Split:  diag[e,i] = scale * sum_l s[i,l]*emb1[x1[i,l]][e]      (term1, gather)
//                   +          sum_l s[i,l]*pe[l][e]             (term2, dense GEMM)
// with    s[i,l] = emb2[x2[i,l]][i]*scale + pe[l][i]

#define D     300
#define LSEQ  512
#define OUTC  4
#define NCH   4
#define CHUNK 128   // LSEQ / NCH

__device__ float g_pe[LSEQ * D];          // [l][d]
__device__ float g_s[D * LSEQ];           // [i][l]
__device__ float g_part[NCH * D * D];     // [chunk][i][e]  (term1 partials)
__device__ float g_dpart[2 * D * D];      // diag partials [kz][e][i]
__device__ float g_hpart[3 * D * D];      // fc1 partials  [kz][e][j]

// ---------------------------------------------------------------------------
// Kernel 0: positional encoding, float32 (matches jnp float32 path).
// ---------------------------------------------------------------------------
__global__ void pe_kernel() {
    int idx = blockIdx.x * blockDim.x + threadIdx.x;
    if (idx >= LSEQ * D) return;
    int l = idx / D;
    int d = idx % D;
    int k = d >> 1;
    const float coef = -9.210340371976184f / (float)D;   // -ln(10000)/300
    float divv = expf((float)(2 * k) * coef);
    float ang  = (float)l * divv;
    g_pe[idx] = (d & 1) ? cosf(ang) : sinf(ang);
}

// ---------------------------------------------------------------------------
// Kernel 1: term1 partials. One block per (i, l-chunk).
// ---------------------------------------------------------------------------
__global__ __launch_bounds__(320) void term1_kernel(
    const int*   __restrict__ x1,
    const int*   __restrict__ x2,
    const float* __restrict__ emb1,
    const float* __restrict__ emb2)
{
    const int chunk = blockIdx.x;          // 0..3
    const int i     = blockIdx.y;          // 0..299
    const int tid   = threadIdx.x;
    const float scale = 17.320508075688775f;  // sqrt(300)

    __shared__ float s_sh[CHUNK];
    __shared__ int   r1_sh[CHUNK];

    if (tid < CHUNK) {
        int l  = chunk * CHUNK + tid;
        int t2 = x2[i * LSEQ + l];
        float sv = fmaf(emb2[t2 * D + i], scale, g_pe[l * D + i]);
        s_sh[tid] = sv;
        g_s[i * LSEQ + l] = sv;
        r1_sh[tid] = x1[i * LSEQ + l] * D;
    }
    __syncthreads();

    if (tid < D) {
        const int e = tid;
        float acc[8];
        #pragma unroll
        for (int u = 0; u < 8; ++u) acc[u] = 0.f;
        #pragma unroll 2
        for (int l = 0; l < CHUNK; l += 8) {
            #pragma unroll
            for (int u = 0; u < 8; ++u)
                acc[u] = fmaf(s_sh[l + u], emb1[r1_sh[l + u] + e], acc[u]);
        }
        float r = ((acc[0] + acc[1]) + (acc[2] + acc[3]))
                + ((acc[4] + acc[5]) + (acc[6] + acc[7]));
        g_part[(chunk * D + i) * D + e] = r;
    }
}

// ---------------------------------------------------------------------------
// Kernel 2: term2 GEMM partials + term1 reduction (kz==0 only).
//   g_dpart[kz][e][i] = sum_{l in half kz} s[i,l]*pe[l][e]
//                       (+ scale*sum_c part[c][i][e] when kz==0)
// grid (10,10,2), 128 threads (16,8). Thread tile 2e x 4i.
// ---------------------------------------------------------------------------
__global__ __launch_bounds__(128) void combine_kernel()
{
    __shared__ float sh_s[32][129];    // [i_local][k_local]
    __shared__ float sh_pe[128][33];   // [k_local][e_local]

    const int tx  = threadIdx.x;       // 0..15 -> e (x2)
    const int ty  = threadIdx.y;       // 0..7  -> i (x4)
    const int lin = ty * 16 + tx;
    const int e0  = blockIdx.x * 32;
    const int i0  = blockIdx.y * 32;
    const int kz  = blockIdx.z;        // 0..1
    const int kbase = kz * 256;

    const float scale = 17.320508075688775f;

    float acc[2][4];
    #pragma unroll
    for (int jj = 0; jj < 2; ++jj)
        #pragma unroll
        for (int u = 0; u < 4; ++u) acc[jj][u] = 0.f;

    #pragma unroll
    for (int st = 0; st < 2; ++st) {
        const int kb = kbase + st * 128;
        // stage s tile: 32 i-rows x 128 k (float4)
        #pragma unroll
        for (int t = 0; t < 8; ++t) {
            int idx = lin + t * 128;           // 0..1023
            int row = idx >> 5;                // 0..31
            int kk  = (idx & 31) * 4;          // 0..124
            float4 v = make_float4(0.f, 0.f, 0.f, 0.f);
            int ii = i0 + row;
            if (ii < D)
                v = *reinterpret_cast<const float4*>(g_s + ii * LSEQ + kb + kk);
            sh_s[row][kk] = v.x; sh_s[row][kk + 1] = v.y;
            sh_s[row][kk + 2] = v.z; sh_s[row][kk + 3] = v.w;
        }
        // stage pe tile: 128 k-rows x 32 e (float4)
        #pragma unroll
        for (int t = 0; t < 8; ++t) {
            int idx = lin + t * 128;           // 0..1023
            int row = idx >> 3;                // 0..127
            int cc  = (idx & 7) * 4;           // 0..28
            int e   = e0 + cc;
            float4 v = make_float4(0.f, 0.f, 0.f, 0.f);
            if (e <= D - 4)
                v = *reinterpret_cast<const float4*>(g_pe + (kb + row) * D + e);
            sh_pe[row][cc] = v.x; sh_pe[row][cc + 1] = v.y;
            sh_pe[row][cc + 2] = v.z; sh_pe[row][cc + 3] = v.w;
        }
        __syncthreads();

        #pragma unroll 4
        for (int k = 0; k < 128; ++k) {
            float p0 = sh_pe[k][tx];
            float p1 = sh_pe[k][tx + 16];
            float s0 = sh_s[ty][k];
            float s1 = sh_s[ty + 8][k];
            float s2 = sh_s[ty + 16][k];
            float s3 = sh_s[ty + 24][k];
            acc[0][0] = fmaf(s0, p0, acc[0][0]);
            acc[0][1] = fmaf(s1, p0, acc[0][1]);
            acc[0][2] = fmaf(s2, p0, acc[0][2]);
            acc[0][3] = fmaf(s3, p0, acc[0][3]);
            acc[1][0] = fmaf(s0, p1, acc[1][0]);
            acc[1][1] = fmaf(s1, p1, acc[1][1]);
            acc[1][2] = fmaf(s2, p1, acc[1][2]);
            acc[1][3] = fmaf(s3, p1, acc[1][3]);
        }
        __syncthreads();
    }

    #pragma unroll
    for (int jj = 0; jj < 2; ++jj) {
        int e = e0 + tx + 16 * jj;
        if (e < D) {
            #pragma unroll
            for (int u = 0; u < 4; ++u) {
                int i = i0 + ty + 8 * u;
                if (i < D) {
                    float r = acc[jj][u];
                    if (kz == 0) {
                        float p = g_part[(0 * D + i) * D + e]
                                + g_part[(1 * D + i) * D + e]
                                + g_part[(2 * D + i) * D + e]
                                + g_part[(3 * D + i) * D + e];
                        r = fmaf(scale, p, r);
                    }
                    g_dpart[kz * D * D + e * D + i] = r;
                }
            }
        }
    }
}

// ---------------------------------------------------------------------------
// Kernel 3: FC1 partials. grid (10,10,3): kz -> K window of 100.
//   g_hpart[kz][e][j] = sum_{k in window} diag[e][k] * w1[j][k]
// diag[e][k] = g_dpart[0][e][k] + g_dpart[1][e][k] (summed at staging).
// 128 threads (16,8), thread tile 2j x 4e. Bias/ReLU deferred to fc2.
// ---------------------------------------------------------------------------
#define KT1 100
__global__ __launch_bounds__(128) void fc1_kernel(
    const float* __restrict__ w1)
{
    __shared__ float sa[32][KT1 + 1];   // diag tile [e][k], stride 101
    __shared__ float sb[32][KT1 + 1];   // w1   tile [j][k]

    const int tx  = threadIdx.x;        // 0..15 -> j (x2)
    const int ty  = threadIdx.y;        // 0..7  -> e (x4)
    const int lin = ty * 16 + tx;
    const int j0  = blockIdx.x * 32;
    const int e0  = blockIdx.y * 32;
    const int kb  = blockIdx.z * KT1;

    float acc[2][4];
    #pragma unroll
    for (int jj = 0; jj < 2; ++jj)
        #pragma unroll
        for (int u = 0; u < 4; ++u) acc[jj][u] = 0.f;

    // stage: 32 rows x 25 float4 per operand
    for (int idx = lin; idx < 32 * 25; idx += 128) {
        int row = idx / 25;
        int kk  = (idx % 25) * 4;
        int k   = kb + kk;                 // kb+96+3 = max 299 < 300, always valid
        float4 va = make_float4(0.f, 0.f, 0.f, 0.f);
        float4 vb = va;
        if (e0 + row < D) {
            float4 v0 = *reinterpret_cast<const float4*>(g_dpart + (e0 + row) * D + k);
            float4 v1 = *reinterpret_cast<const float4*>(g_dpart + D * D + (e0 + row) * D + k);
            va = make_float4(v0.x + v1.x, v0.y + v1.y, v0.z + v1.z, v0.w + v1.w);
        }
        if (j0 + row < D)
            vb = *reinterpret_cast<const float4*>(w1 + (j0 + row) * D + k);
        sa[row][kk] = va.x; sa[row][kk + 1] = va.y;
        sa[row][kk + 2] = va.z; sa[row][kk + 3] = va.w;
        sb[row][kk] = vb.x; sb[row][kk + 1] = vb.y;
        sb[row][kk + 2] = vb.z; sb[row][kk + 3] = vb.w;
    }
    __syncthreads();

    #pragma unroll 4
    for (int k = 0; k < KT1; ++k) {
        float b0 = sb[tx][k];
        float b1v = sb[tx + 16][k];
        float a0 = sa[ty][k];
        float a1 = sa[ty + 8][k];
        float a2 = sa[ty + 16][k];
        float a3 = sa[ty + 24][k];
        acc[0][0] = fmaf(b0, a0, acc[0][0]);
        acc[0][1] = fmaf(b0, a1, acc[0][1]);
        acc[0][2] = fmaf(b0, a2, acc[0][2]);
        acc[0][3] = fmaf(b0, a3, acc[0][3]);
        acc[1][0] = fmaf(b1v, a0, acc[1][0]);
        acc[1][1] = fmaf(b1v, a1, acc[1][1]);
        acc[1][2] = fmaf(b1v, a2, acc[1][2]);
        acc[1][3] = fmaf(b1v, a3, acc[1][3]);
    }

    const int kz = blockIdx.z;
    #pragma unroll
    for (int jj = 0; jj < 2; ++jj) {
        int j = j0 + tx + 16 * jj;
        if (j < D) {
            #pragma unroll
            for (int u = 0; u < 4; ++u) {
                int e = e0 + ty + 8 * u;
                if (e < D) g_hpart[kz * D * D + e * D + j] = acc[jj][u];
            }
        }
    }
}

// ---------------------------------------------------------------------------
// Kernel 4: FC2 + softmax. One block per e-row. Folds hpart sum + bias + relu.
// ---------------------------------------------------------------------------
__global__ __launch_bounds__(128) void fc2_kernel(
    const float* __restrict__ b1,
    const float* __restrict__ w2,
    const float* __restrict__ b2,
    float*       __restrict__ out)
{
    const int e   = blockIdx.x;
    const int tid = threadIdx.x;

    float p[OUTC] = {0.f, 0.f, 0.f, 0.f};
    for (int j = tid; j < D; j += 128) {
        float hv = g_hpart[e * D + j]
                 + g_hpart[D * D + e * D + j]
                 + g_hpart[2 * D * D + e * D + j]
                 + b1[j];
        hv = fmaxf(hv, 0.f);
        #pragma unroll
        for (int o = 0; o < OUTC; ++o)
            p[o] = fmaf(hv, w2[o * D + j], p[o]);
    }

    #pragma unroll
    for (int off = 16; off > 0; off >>= 1) {
        #pragma unroll
        for (int o = 0; o < OUTC; ++o)
            p[o] += __shfl_xor_sync(0xFFFFFFFFu, p[o], off);
    }

    __shared__ float red[4][OUTC];
    const int wid = tid >> 5, lid = tid & 31;
    if (lid == 0) {
        #pragma unroll
        for (int o = 0; o < OUTC; ++o) red[wid][o] = p[o];
    }
    __syncthreads();

    if (tid == 0) {
        float logits[OUTC];
        #pragma unroll
        for (int o = 0; o < OUTC; ++o)
            logits[o] = red[0][o] + red[1][o] + red[2][o] + red[3][o] + b2[o];
        float m = fmaxf(fmaxf(logits[0], logits[1]), fmaxf(logits[2], logits[3]));
        float es[OUTC], ssum = 0.f;
        #pragma unroll
        for (int o = 0; o < OUTC; ++o) { es[o] = expf(logits[o] - m); ssum += es[o]; }
        float inv = 1.f / ssum;
        #pragma unroll
        for (int o = 0; o < OUTC; ++o) out[e * OUTC + o] = es[o] * inv;
    }
}

// ---------------------------------------------------------------------------
// Launch. Inputs: x1, x2 (i32 [512*512]); emb1, emb2 (f32 [32000*300]);
// w1 (f32 [300*300]); b1 (f32 [300]); w2 (f32 [4*300]); b2 (f32 [4]).
// Output: f32 [300*4].
// ---------------------------------------------------------------------------
extern "C" void kernel_launch(void* const* d_in, const int* in_sizes, int n_in,
                              void* d_out, int out_size) {
    const int*   x1   = (const int*)  d_in[0];
    const int*   x2   = (const int*)  d_in[1];
    const float* emb1 = (const float*)d_in[2];
    const float* emb2 = (const float*)d_in[3];
    const float* w1   = (const float*)d_in[4];
    const float* b1   = (const float*)d_in[5];
    const float* w2   = (const float*)d_in[6];
    const float* b2   = (const float*)d_in[7];
    float* out = (float*)d_out;

    pe_kernel<<<(LSEQ * D + 255) / 256, 256>>>();
    dim3 g1(NCH, D);
    term1_kernel<<<g1, 320>>>(x1, x2, emb1, emb2);
    combine_kernel<<<dim3(10, 10, 2), dim3(16, 8)>>>();
    fc1_kernel<<<dim3(10, 10, 3), dim3(16, 8)>>>(w1);
    fc2_kernel<<<D, 128>>>(b1, w2, b2, out);
}

// round 6
// speedup vs baseline: 2.7770x; 1.0877x over previous
#include <cuda_runtime.h>
#include <math.h>

// D_MODEL=300, L=512, B=512, OUT=4.
// diag[e,i] = fmap[i,i,e] = sum_l e2[i,l,i] * e1[i,l,e], i in [0,300)
// Split:  diag[e,i] = scale * sum_l s[i,l]*emb1[x1[i,l]][e]      (term1, gather)
//                   +          sum_l s[i,l]*pe[l][e]             (term2, dense GEMM)
// with    s[i,l] = emb2[x2[i,l]][i]*scale + pe[l][i]

#define D     300
#define LSEQ  512
#define OUTC  4
#define NCH   4
#define CHUNK 128   // LSEQ / NCH
#define DKZ   4     // combine K-split
#define HKZ   5     // fc1 K-split
#define KT1   60    // fc1 K per block (5*60=300)

__device__ float g_pe[LSEQ * D];          // [l][d]
__device__ float g_s[D * LSEQ];           // [i][l]
__device__ float g_part[NCH * D * D];     // [chunk][i][e]  (term1 partials)
__device__ float g_dpart[DKZ * D * D];    // diag partials [kz][e][i]
__device__ float g_hpart[HKZ * D * D];    // fc1 partials  [kz][e][j]

// ---------------------------------------------------------------------------
// Kernel 0: positional encoding, float32 (matches jnp float32 path).
// ---------------------------------------------------------------------------
__global__ void pe_kernel() {
    int idx = blockIdx.x * blockDim.x + threadIdx.x;
    if (idx >= LSEQ * D) return;
    int l = idx / D;
    int d = idx % D;
    int k = d >> 1;
    const float coef = -9.210340371976184f / (float)D;   // -ln(10000)/300
    float divv = expf((float)(2 * k) * coef);
    float ang  = (float)l * divv;
    g_pe[idx] = (d & 1) ? cosf(ang) : sinf(ang);
}

// ---------------------------------------------------------------------------
// Kernel 1: term1 partials. One block per (i, l-chunk).
// ---------------------------------------------------------------------------
__global__ __launch_bounds__(320) void term1_kernel(
    const int*   __restrict__ x1,
    const int*   __restrict__ x2,
    const float* __restrict__ emb1,
    const float* __restrict__ emb2)
{
    const int chunk = blockIdx.x;          // 0..3
    const int i     = blockIdx.y;          // 0..299
    const int tid   = threadIdx.x;
    const float scale = 17.320508075688775f;  // sqrt(300)

    __shared__ float s_sh[CHUNK];
    __shared__ int   r1_sh[CHUNK];

    if (tid < CHUNK) {
        int l  = chunk * CHUNK + tid;
        int t2 = x2[i * LSEQ + l];
        float sv = fmaf(emb2[t2 * D + i], scale, g_pe[l * D + i]);
        s_sh[tid] = sv;
        g_s[i * LSEQ + l] = sv;
        r1_sh[tid] = x1[i * LSEQ + l] * D;
    }
    __syncthreads();

    if (tid < D) {
        const int e = tid;
        float acc[8];
        #pragma unroll
        for (int u = 0; u < 8; ++u) acc[u] = 0.f;
        #pragma unroll 2
        for (int l = 0; l < CHUNK; l += 8) {
            #pragma unroll
            for (int u = 0; u < 8; ++u)
                acc[u] = fmaf(s_sh[l + u], emb1[r1_sh[l + u] + e], acc[u]);
        }
        float r = ((acc[0] + acc[1]) + (acc[2] + acc[3]))
                + ((acc[4] + acc[5]) + (acc[6] + acc[7]));
        g_part[(chunk * D + i) * D + e] = r;
    }
}

// ---------------------------------------------------------------------------
// Kernel 2: term2 GEMM partials + term1 reduction (kz==0 only).
//   g_dpart[kz][e][i] = sum_{l in 128-window kz} s[i,l]*pe[l][e]
//                       (+ scale*sum_c part[c][i][e] when kz==0)
// grid (10,10,4), 128 threads (16,8). Thread tile 2e x 4i. One smem stage.
// ---------------------------------------------------------------------------
__global__ __launch_bounds__(128) void combine_kernel()
{
    __shared__ float sh_s[32][129];    // [i_local][k_local]
    __shared__ float sh_pe[128][33];   // [k_local][e_local]

    const int tx  = threadIdx.x;       // 0..15 -> e (x2)
    const int ty  = threadIdx.y;       // 0..7  -> i (x4)
    const int lin = ty * 16 + tx;
    const int e0  = blockIdx.x * 32;
    const int i0  = blockIdx.y * 32;
    const int kz  = blockIdx.z;        // 0..3
    const int kb  = kz * 128;

    const float scale = 17.320508075688775f;

    float acc[2][4];
    #pragma unroll
    for (int jj = 0; jj < 2; ++jj)
        #pragma unroll
        for (int u = 0; u < 4; ++u) acc[jj][u] = 0.f;

    // stage s tile: 32 i-rows x 128 k (float4)
    #pragma unroll
    for (int t = 0; t < 8; ++t) {
        int idx = lin + t * 128;           // 0..1023
        int row = idx >> 5;                // 0..31
        int kk  = (idx & 31) * 4;          // 0..124
        float4 v = make_float4(0.f, 0.f, 0.f, 0.f);
        int ii = i0 + row;
        if (ii < D)
            v = *reinterpret_cast<const float4*>(g_s + ii * LSEQ + kb + kk);
        sh_s[row][kk] = v.x; sh_s[row][kk + 1] = v.y;
        sh_s[row][kk + 2] = v.z; sh_s[row][kk + 3] = v.w;
    }
    // stage pe tile: 128 k-rows x 32 e (float4)
    #pragma unroll
    for (int t = 0; t < 8; ++t) {
        int idx = lin + t * 128;           // 0..1023
        int row = idx >> 3;                // 0..127
        int cc  = (idx & 7) * 4;           // 0..28
        int e   = e0 + cc;
        float4 v = make_float4(0.f, 0.f, 0.f, 0.f);
        if (e <= D - 4)
            v = *reinterpret_cast<const float4*>(g_pe + (kb + row) * D + e);
        sh_pe[row][cc] = v.x; sh_pe[row][cc + 1] = v.y;
        sh_pe[row][cc + 2] = v.z; sh_pe[row][cc + 3] = v.w;
    }
    __syncthreads();

    #pragma unroll 4
    for (int k = 0; k < 128; ++k) {
        float p0 = sh_pe[k][tx];
        float p1 = sh_pe[k][tx + 16];
        float s0 = sh_s[ty][k];
        float s1 = sh_s[ty + 8][k];
        float s2 = sh_s[ty + 16][k];
        float s3 = sh_s[ty + 24][k];
        acc[0][0] = fmaf(s0, p0, acc[0][0]);
        acc[0][1] = fmaf(s1, p0, acc[0][1]);
        acc[0][2] = fmaf(s2, p0, acc[0][2]);
        acc[0][3] = fmaf(s3, p0, acc[0][3]);
        acc[1][0] = fmaf(s0, p1, acc[1][0]);
        acc[1][1] = fmaf(s1, p1, acc[1][1]);
        acc[1][2] = fmaf(s2, p1, acc[1][2]);
        acc[1][3] = fmaf(s3, p1, acc[1][3]);
    }

    #pragma unroll
    for (int jj = 0; jj < 2; ++jj) {
        int e = e0 + tx + 16 * jj;
        if (e < D) {
            #pragma unroll
            for (int u = 0; u < 4; ++u) {
                int i = i0 + ty + 8 * u;
                if (i < D) {
                    float r = acc[jj][u];
                    if (kz == 0) {
                        float p = g_part[(0 * D + i) * D + e]
                                + g_part[(1 * D + i) * D + e]
                                + g_part[(2 * D + i) * D + e]
                                + g_part[(3 * D + i) * D + e];
                        r = fmaf(scale, p, r);
                    }
                    g_dpart[kz * D * D + e * D + i] = r;
                }
            }
        }
    }
}

// ---------------------------------------------------------------------------
// Kernel 3: FC1 partials. grid (10,10,5): kz -> K window of 60.
//   g_hpart[kz][e][j] = sum_{k in window} diag[e][k] * w1[j][k]
// diag[e][k] = sum of 4 dpart planes (summed at staging).
// 128 threads (16,8), thread tile 2j x 4e. Bias/ReLU deferred to fc2.
// ---------------------------------------------------------------------------
__global__ __launch_bounds__(128) void fc1_kernel(
    const float* __restrict__ w1)
{
    __shared__ float sa[32][KT1 + 1];   // diag tile [e][k], stride 61
    __shared__ float sb[32][KT1 + 1];   // w1   tile [j][k]

    const int tx  = threadIdx.x;        // 0..15 -> j (x2)
    const int ty  = threadIdx.y;        // 0..7  -> e (x4)
    const int lin = ty * 16 + tx;
    const int j0  = blockIdx.x * 32;
    const int e0  = blockIdx.y * 32;
    const int kb  = blockIdx.z * KT1;

    float acc[2][4];
    #pragma unroll
    for (int jj = 0; jj < 2; ++jj)
        #pragma unroll
        for (int u = 0; u < 4; ++u) acc[jj][u] = 0.f;

    // stage: 32 rows x 15 float4 per operand (480 loads per operand)
    for (int idx = lin; idx < 32 * 15; idx += 128) {
        int row = idx / 15;
        int kk  = (idx % 15) * 4;
        int k   = kb + kk;                 // max 240+56+3 = 299 < 300
        float4 va = make_float4(0.f, 0.f, 0.f, 0.f);
        float4 vb = va;
        if (e0 + row < D) {
            float4 v0 = *reinterpret_cast<const float4*>(g_dpart + 0 * D * D + (e0 + row) * D + k);
            float4 v1 = *reinterpret_cast<const float4*>(g_dpart + 1 * D * D + (e0 + row) * D + k);
            float4 v2 = *reinterpret_cast<const float4*>(g_dpart + 2 * D * D + (e0 + row) * D + k);
            float4 v3 = *reinterpret_cast<const float4*>(g_dpart + 3 * D * D + (e0 + row) * D + k);
            va = make_float4((v0.x + v1.x) + (v2.x + v3.x),
                             (v0.y + v1.y) + (v2.y + v3.y),
                             (v0.z + v1.z) + (v2.z + v3.z),
                             (v0.w + v1.w) + (v2.w + v3.w));
        }
        if (j0 + row < D)
            vb = *reinterpret_cast<const float4*>(w1 + (j0 + row) * D + k);
        sa[row][kk] = va.x; sa[row][kk + 1] = va.y;
        sa[row][kk + 2] = va.z; sa[row][kk + 3] = va.w;
        sb[row][kk] = vb.x; sb[row][kk + 1] = vb.y;
        sb[row][kk + 2] = vb.z; sb[row][kk + 3] = vb.w;
    }
    __syncthreads();

    #pragma unroll 4
    for (int k = 0; k < KT1; ++k) {
        float b0 = sb[tx][k];
        float b1v = sb[tx + 16][k];
        float a0 = sa[ty][k];
        float a1 = sa[ty + 8][k];
        float a2 = sa[ty + 16][k];
        float a3 = sa[ty + 24][k];
        acc[0][0] = fmaf(b0, a0, acc[0][0]);
        acc[0][1] = fmaf(b0, a1, acc[0][1]);
        acc[0][2] = fmaf(b0, a2, acc[0][2]);
        acc[0][3] = fmaf(b0, a3, acc[0][3]);
        acc[1][0] = fmaf(b1v, a0, acc[1][0]);
        acc[1][1] = fmaf(b1v, a1, acc[1][1]);
        acc[1][2] = fmaf(b1v, a2, acc[1][2]);
        acc[1][3] = fmaf(b1v, a3, acc[1][3]);
    }

    const int kz = blockIdx.z;
    #pragma unroll
    for (int jj = 0; jj < 2; ++jj) {
        int j = j0 + tx + 16 * jj;
        if (j < D) {
            #pragma unroll
            for (int u = 0; u < 4; ++u) {
                int e = e0 + ty + 8 * u;
                if (e < D) g_hpart[kz * D * D + e * D + j] = acc[jj][u];
            }
        }
    }
}

// ---------------------------------------------------------------------------
// Kernel 4: FC2 + softmax. One block per e-row. Folds hpart sum + bias + relu.
// ---------------------------------------------------------------------------
__global__ __launch_bounds__(128) void fc2_kernel(
    const float* __restrict__ b1,
    const float* __restrict__ w2,
    const float* __restrict__ b2,
    float*       __restrict__ out)
{
    const int e   = blockIdx.x;
    const int tid = threadIdx.x;

    float p[OUTC] = {0.f, 0.f, 0.f, 0.f};
    for (int j = tid; j < D; j += 128) {
        float hv = b1[j];
        #pragma unroll
        for (int z = 0; z < HKZ; ++z)
            hv += g_hpart[z * D * D + e * D + j];
        hv = fmaxf(hv, 0.f);
        #pragma unroll
        for (int o = 0; o < OUTC; ++o)
            p[o] = fmaf(hv, w2[o * D + j], p[o]);
    }

    #pragma unroll
    for (int off = 16; off > 0; off >>= 1) {
        #pragma unroll
        for (int o = 0; o < OUTC; ++o)
            p[o] += __shfl_xor_sync(0xFFFFFFFFu, p[o], off);
    }

    __shared__ float red[4][OUTC];
    const int wid = tid >> 5, lid = tid & 31;
    if (lid == 0) {
        #pragma unroll
        for (int o = 0; o < OUTC; ++o) red[wid][o] = p[o];
    }
    __syncthreads();

    if (tid == 0) {
        float logits[OUTC];
        #pragma unroll
        for (int o = 0; o < OUTC; ++o)
            logits[o] = red[0][o] + red[1][o] + red[2][o] + red[3][o] + b2[o];
        float m = fmaxf(fmaxf(logits[0], logits[1]), fmaxf(logits[2], logits[3]));
        float es[OUTC], ssum = 0.f;
        #pragma unroll
        for (int o = 0; o < OUTC; ++o) { es[o] = expf(logits[o] - m); ssum += es[o]; }
        float inv = 1.f / ssum;
        #pragma unroll
        for (int o = 0; o < OUTC; ++o) out[e * OUTC + o] = es[o] * inv;
    }
}

// ---------------------------------------------------------------------------
// Launch. Inputs: x1, x2 (i32 [512*512]); emb1, emb2 (f32 [32000*300]);
// w1 (f32 [300*300]); b1 (f32 [300]); w2 (f32 [4*300]); b2 (f32 [4]).
// Output: f32 [300*4].
// ---------------------------------------------------------------------------
extern "C" void kernel_launch(void* const* d_in, const int* in_sizes, int n_in,
                              void* d_out, int out_size) {
    const int*   x1   = (const int*)  d_in[0];
    const int*   x2   = (const int*)  d_in[1];
    const float* emb1 = (const float*)d_in[2];
    const float* emb2 = (const float*)d_in[3];
    const float* w1   = (const float*)d_in[4];
    const float* b1   = (const float*)d_in[5];
    const float* w2   = (const float*)d_in[6];
    const float* b2   = (const float*)d_in[7];
    float* out = (float*)d_out;

    pe_kernel<<<(LSEQ * D + 255) / 256, 256>>>();
    dim3 g1(NCH, D);
    term1_kernel<<<g1, 320>>>(x1, x2, emb1, emb2);
    combine_kernel<<<dim3(10, 10, DKZ), dim3(16, 8)>>>();
    fc1_kernel<<<dim3(10, 10, HKZ), dim3(16, 8)>>>(w1);
    fc2_kernel<<<D, 128>>>(b1, w2, b2, out);
}

// round 7
// speedup vs baseline: 2.7954x; 1.0066x over previous
#include <cuda_runtime.h>
#include <math.h>

// D_MODEL=300, L=512, B=512, OUT=4.
// diag[e,i] = fmap[i,i,e] = sum_l e2[i,l,i] * e1[i,l,e], i in [0,300)
// Split:  diag[e,i] = scale * sum_l s[i,l]*emb1[x1[i,l]][e]      (term1, gather)
//                   +          sum_l s[i,l]*pe[l][e]             (term2, dense GEMM)
// with    s[i,l] = emb2[x2[i,l]][i]*scale + pe[l][i]

#define D     300
#define LSEQ  512
#define OUTC  4
#define NCH   8     // term1 l-split
#define CHUNK 64    // LSEQ / NCH
#define DKZ   8     // combine K-split (64 per block)
#define HKZ   5     // fc1 K-split
#define KT1   60    // fc1 K per block (5*60=300)

__device__ float g_pe[LSEQ * D];          // [l][d]
__device__ float g_s[D * LSEQ];           // [i][l]
__device__ float g_part[NCH * D * D];     // [chunk][i][e]  (term1 partials)
__device__ float g_dpart[DKZ * D * D];    // diag partials [kz][e][i]
__device__ float g_hpart[HKZ * D * D];    // fc1 partials  [kz][e][j]

// ---------------------------------------------------------------------------
// Kernel 0: positional encoding, float32 (matches jnp float32 path).
// ---------------------------------------------------------------------------
__global__ void pe_kernel() {
    int idx = blockIdx.x * blockDim.x + threadIdx.x;
    if (idx >= LSEQ * D) return;
    int l = idx / D;
    int d = idx % D;
    int k = d >> 1;
    const float coef = -9.210340371976184f / (float)D;   // -ln(10000)/300
    float divv = expf((float)(2 * k) * coef);
    float ang  = (float)l * divv;
    g_pe[idx] = (d & 1) ? cosf(ang) : sinf(ang);
}

// ---------------------------------------------------------------------------
// Kernel 1: term1 partials. One block per (i, l-chunk of 64). grid (8,300).
// ---------------------------------------------------------------------------
__global__ __launch_bounds__(320) void term1_kernel(
    const int*   __restrict__ x1,
    const int*   __restrict__ x2,
    const float* __restrict__ emb1,
    const float* __restrict__ emb2)
{
    const int chunk = blockIdx.x;          // 0..7
    const int i     = blockIdx.y;          // 0..299
    const int tid   = threadIdx.x;
    const float scale = 17.320508075688775f;  // sqrt(300)

    __shared__ float s_sh[CHUNK];
    __shared__ int   r1_sh[CHUNK];

    if (tid < CHUNK) {
        int l  = chunk * CHUNK + tid;
        int t2 = x2[i * LSEQ + l];
        float sv = fmaf(emb2[t2 * D + i], scale, g_pe[l * D + i]);
        s_sh[tid] = sv;
        g_s[i * LSEQ + l] = sv;
        r1_sh[tid] = x1[i * LSEQ + l] * D;
    }
    __syncthreads();

    if (tid < D) {
        const int e = tid;
        float acc[8];
        #pragma unroll
        for (int u = 0; u < 8; ++u) acc[u] = 0.f;
        #pragma unroll
        for (int l = 0; l < CHUNK; l += 8) {
            #pragma unroll
            for (int u = 0; u < 8; ++u)
                acc[u] = fmaf(s_sh[l + u], emb1[r1_sh[l + u] + e], acc[u]);
        }
        float r = ((acc[0] + acc[1]) + (acc[2] + acc[3]))
                + ((acc[4] + acc[5]) + (acc[6] + acc[7]));
        g_part[(chunk * D + i) * D + e] = r;
    }
}

// ---------------------------------------------------------------------------
// Kernel 2: term2 GEMM partials + term1 reduction (kz==0 only).
//   g_dpart[kz][e][i] = sum_{l in 64-window kz} s[i,l]*pe[l][e]
//                       (+ scale*sum_c part[c][i][e] when kz==0)
// grid (10,10,8), 128 threads (16,8). Thread tile 2e x 4i.
// ---------------------------------------------------------------------------
__global__ __launch_bounds__(128) void combine_kernel()
{
    __shared__ float sh_s[32][65];     // [i_local][k_local]
    __shared__ float sh_pe[64][33];    // [k_local][e_local]

    const int tx  = threadIdx.x;       // 0..15 -> e (x2)
    const int ty  = threadIdx.y;       // 0..7  -> i (x4)
    const int lin = ty * 16 + tx;
    const int e0  = blockIdx.x * 32;
    const int i0  = blockIdx.y * 32;
    const int kz  = blockIdx.z;        // 0..7
    const int kb  = kz * 64;

    const float scale = 17.320508075688775f;

    float acc[2][4];
    #pragma unroll
    for (int jj = 0; jj < 2; ++jj)
        #pragma unroll
        for (int u = 0; u < 4; ++u) acc[jj][u] = 0.f;

    // stage s tile: 32 i-rows x 64 k (16 float4 per row)
    #pragma unroll
    for (int t = 0; t < 4; ++t) {
        int idx = lin + t * 128;           // 0..511
        int row = idx >> 4;                // 0..31
        int kk  = (idx & 15) * 4;          // 0..60
        float4 v = make_float4(0.f, 0.f, 0.f, 0.f);
        int ii = i0 + row;
        if (ii < D)
            v = *reinterpret_cast<const float4*>(g_s + ii * LSEQ + kb + kk);
        sh_s[row][kk] = v.x; sh_s[row][kk + 1] = v.y;
        sh_s[row][kk + 2] = v.z; sh_s[row][kk + 3] = v.w;
    }
    // stage pe tile: 64 k-rows x 32 e (8 float4 per row)
    #pragma unroll
    for (int t = 0; t < 4; ++t) {
        int idx = lin + t * 128;           // 0..511
        int row = idx >> 3;                // 0..63
        int cc  = (idx & 7) * 4;           // 0..28
        int e   = e0 + cc;
        float4 v = make_float4(0.f, 0.f, 0.f, 0.f);
        if (e <= D - 4)
            v = *reinterpret_cast<const float4*>(g_pe + (kb + row) * D + e);
        sh_pe[row][cc] = v.x; sh_pe[row][cc + 1] = v.y;
        sh_pe[row][cc + 2] = v.z; sh_pe[row][cc + 3] = v.w;
    }
    __syncthreads();

    #pragma unroll 4
    for (int k = 0; k < 64; ++k) {
        float p0 = sh_pe[k][tx];
        float p1 = sh_pe[k][tx + 16];
        float s0 = sh_s[ty][k];
        float s1 = sh_s[ty + 8][k];
        float s2 = sh_s[ty + 16][k];
        float s3 = sh_s[ty + 24][k];
        acc[0][0] = fmaf(s0, p0, acc[0][0]);
        acc[0][1] = fmaf(s1, p0, acc[0][1]);
        acc[0][2] = fmaf(s2, p0, acc[0][2]);
        acc[0][3] = fmaf(s3, p0, acc[0][3]);
        acc[1][0] = fmaf(s0, p1, acc[1][0]);
        acc[1][1] = fmaf(s1, p1, acc[1][1]);
        acc[1][2] = fmaf(s2, p1, acc[1][2]);
        acc[1][3] = fmaf(s3, p1, acc[1][3]);
    }

    #pragma unroll
    for (int jj = 0; jj < 2; ++jj) {
        int e = e0 + tx + 16 * jj;
        if (e < D) {
            #pragma unroll
            for (int u = 0; u < 4; ++u) {
                int i = i0 + ty + 8 * u;
                if (i < D) {
                    float r = acc[jj][u];
                    if (kz == 0) {
                        float p = 0.f;
                        #pragma unroll
                        for (int c = 0; c < NCH; ++c)
                            p += g_part[(c * D + i) * D + e];
                        r = fmaf(scale, p, r);
                    }
                    g_dpart[kz * D * D + e * D + i] = r;
                }
            }
        }
    }
}

// ---------------------------------------------------------------------------
// Kernel 3: FC1 partials. grid (10,10,5): kz -> K window of 60.
//   g_hpart[kz][e][j] = sum_{k in window} diag[e][k] * w1[j][k]
// diag[e][k] = sum of 8 dpart planes (summed at staging).
// Transposed k-major smem tiles (pad 36 keeps float4 16B-aligned:
// 144k % 16 == 0). Thread tile 4 contiguous e x 2 contiguous j:
// inner iter = 1 LDS.128 + 1 LDS.64 + 8 FMA.
// ---------------------------------------------------------------------------
__global__ __launch_bounds__(128) void fc1_kernel(
    const float* __restrict__ w1)
{
    __shared__ float sat[KT1][36];      // [k][e_local]
    __shared__ float sbt[KT1][36];      // [k][j_local]

    const int tx  = threadIdx.x;        // 0..15 -> j = j0 + 2*tx + {0,1}
    const int ty  = threadIdx.y;        // 0..7  -> e = e0 + 4*ty + {0..3}
    const int lin = ty * 16 + tx;
    const int j0  = blockIdx.x * 32;
    const int e0  = blockIdx.y * 32;
    const int kb  = blockIdx.z * KT1;

    float acc0[4] = {0.f, 0.f, 0.f, 0.f};   // j = j0+2tx
    float acc1[4] = {0.f, 0.f, 0.f, 0.f};   // j = j0+2tx+1

    // stage: 32 rows x 15 float4 per operand, written transposed
    for (int idx = lin; idx < 32 * 15; idx += 128) {
        int row = idx / 15;                 // e_local / j_local
        int kk  = (idx % 15) * 4;
        int k   = kb + kk;                  // max 240+56+3 = 299 < 300
        float4 va = make_float4(0.f, 0.f, 0.f, 0.f);
        float4 vb = va;
        if (e0 + row < D) {
            #pragma unroll
            for (int z = 0; z < DKZ; ++z) {
                float4 v = *reinterpret_cast<const float4*>(
                    g_dpart + z * D * D + (e0 + row) * D + k);
                va.x += v.x; va.y += v.y; va.z += v.z; va.w += v.w;
            }
        }
        if (j0 + row < D)
            vb = *reinterpret_cast<const float4*>(w1 + (j0 + row) * D + k);
        sat[kk][row] = va.x; sat[kk + 1][row] = va.y;
        sat[kk + 2][row] = va.z; sat[kk + 3][row] = va.w;
        sbt[kk][row] = vb.x; sbt[kk + 1][row] = vb.y;
        sbt[kk + 2][row] = vb.z; sbt[kk + 3][row] = vb.w;
    }
    __syncthreads();

    #pragma unroll 6
    for (int k = 0; k < KT1; ++k) {
        float4 a = *reinterpret_cast<const float4*>(&sat[k][4 * ty]);
        float2 b = *reinterpret_cast<const float2*>(&sbt[k][2 * tx]);
        acc0[0] = fmaf(b.x, a.x, acc0[0]);
        acc0[1] = fmaf(b.x, a.y, acc0[1]);
        acc0[2] = fmaf(b.x, a.z, acc0[2]);
        acc0[3] = fmaf(b.x, a.w, acc0[3]);
        acc1[0] = fmaf(b.y, a.x, acc1[0]);
        acc1[1] = fmaf(b.y, a.y, acc1[1]);
        acc1[2] = fmaf(b.y, a.z, acc1[2]);
        acc1[3] = fmaf(b.y, a.w, acc1[3]);
    }

    const int kz = blockIdx.z;
    const int jp = j0 + 2 * tx;             // even; pair (jp, jp+1)
    if (jp < D) {                            // D even -> pair fully valid
        #pragma unroll
        for (int u = 0; u < 4; ++u) {
            int e = e0 + 4 * ty + u;
            if (e < D) {
                float2 v = make_float2(acc0[u], acc1[u]);
                *reinterpret_cast<float2*>(g_hpart + kz * D * D + e * D + jp) = v;
            }
        }
    }
}

// ---------------------------------------------------------------------------
// Kernel 4: FC2 + softmax. One block per e-row. Folds hpart sum + bias + relu.
// ---------------------------------------------------------------------------
__global__ __launch_bounds__(128) void fc2_kernel(
    const float* __restrict__ b1,
    const float* __restrict__ w2,
    const float* __restrict__ b2,
    float*       __restrict__ out)
{
    const int e   = blockIdx.x;
    const int tid = threadIdx.x;

    float p[OUTC] = {0.f, 0.f, 0.f, 0.f};
    for (int j = tid; j < D; j += 128) {
        float hv = b1[j];
        #pragma unroll
        for (int z = 0; z < HKZ; ++z)
            hv += g_hpart[z * D * D + e * D + j];
        hv = fmaxf(hv, 0.f);
        #pragma unroll
        for (int o = 0; o < OUTC; ++o)
            p[o] = fmaf(hv, w2[o * D + j], p[o]);
    }

    #pragma unroll
    for (int off = 16; off > 0; off >>= 1) {
        #pragma unroll
        for (int o = 0; o < OUTC; ++o)
            p[o] += __shfl_xor_sync(0xFFFFFFFFu, p[o], off);
    }

    __shared__ float red[4][OUTC];
    const int wid = tid >> 5, lid = tid & 31;
    if (lid == 0) {
        #pragma unroll
        for (int o = 0; o < OUTC; ++o) red[wid][o] = p[o];
    }
    __syncthreads();

    if (tid == 0) {
        float logits[OUTC];
        #pragma unroll
        for (int o = 0; o < OUTC; ++o)
            logits[o] = red[0][o] + red[1][o] + red[2][o] + red[3][o] + b2[o];
        float m = fmaxf(fmaxf(logits[0], logits[1]), fmaxf(logits[2], logits[3]));
        float es[OUTC], ssum = 0.f;
        #pragma unroll
        for (int o = 0; o < OUTC; ++o) { es[o] = expf(logits[o] - m); ssum += es[o]; }
        float inv = 1.f / ssum;
        #pragma unroll
        for (int o = 0; o < OUTC; ++o) out[e * OUTC + o] = es[o] * inv;
    }
}

// ---------------------------------------------------------------------------
// Launch. Inputs: x1, x2 (i32 [512*512]); emb1, emb2 (f32 [32000*300]);
// w1 (f32 [300*300]); b1 (f32 [300]); w2 (f32 [4*300]); b2 (f32 [4]).
// Output: f32 [300*4].
// ---------------------------------------------------------------------------
extern "C" void kernel_launch(void* const* d_in, const int* in_sizes, int n_in,
                              void* d_out, int out_size) {
    const int*   x1   = (const int*)  d_in[0];
    const int*   x2   = (const int*)  d_in[1];
    const float* emb1 = (const float*)d_in[2];
    const float* emb2 = (const float*)d_in[3];
    const float* w1   = (const float*)d_in[4];
    const float* b1   = (const float*)d_in[5];
    const float* w2   = (const float*)d_in[6];
    const float* b2   = (const float*)d_in[7];
    float* out = (float*)d_out;

    pe_kernel<<<(LSEQ * D + 255) / 256, 256>>>();
    dim3 g1(NCH, D);
    term1_kernel<<<g1, 320>>>(x1, x2, emb1, emb2);
    combine_kernel<<<dim3(10, 10, DKZ), dim3(16, 8)>>>();
    fc1_kernel<<<dim3(10, 10, HKZ), dim3(16, 8)>>>(w1);
    fc2_kernel<<<D, 128>>>(b1, w2, b2, out);
}